// round 1
// baseline (speedup 1.0000x reference)
#include <cuda_runtime.h>
#include <math.h>

#define HID     128
#define NCOEF   8
#define NFEAT   (HID * 9)        // 1152 expanded features per row
#define NPROTO  256
#define ROWS    32               // rows per CTA
#define THREADS 256
#define KC      32               // k-chunk for GEMM
#define HS_PITCH 129             // padded pitch for h / x tile (conflict-free scalar access)
#define BS_PITCH 132             // padded pitch for B chunk (16B aligned rows, conflict-free vec access)

#define SMEM_FLOATS (NFEAT*ROWS + ROWS*HS_PITCH + KC*BS_PITCH + 16)

// Device scratch (no allocations allowed)
__device__ float g_W1[NFEAT * HID];
__device__ float g_W2[NFEAT * HID];
__device__ float g_PnT[HID * NPROTO];   // transposed, row-normalized prototypes

// ---------------------------------------------------------------------------
// Prep: build combined KAN weights  W[k=i*9+c][o]
//   c==0   -> base_w[o][i]
//   c>=1   -> spline_w[o][i][c-1] * scaler[o][i]
// ---------------------------------------------------------------------------
__global__ void prep_weights(const float* __restrict__ bw1, const float* __restrict__ sw1,
                             const float* __restrict__ sc1,
                             const float* __restrict__ bw2, const float* __restrict__ sw2,
                             const float* __restrict__ sc2) {
    int idx = blockIdx.x * blockDim.x + threadIdx.x;
    const int total = NFEAT * HID;
    if (idx >= 2 * total) return;
    int layer = idx / total;
    int t = idx - layer * total;
    int k = t / HID;
    int o = t - k * HID;
    int i = k / 9;
    int c = k - i * 9;
    const float* bw = layer ? bw2 : bw1;
    const float* sw = layer ? sw2 : sw1;
    const float* sc = layer ? sc2 : sc1;
    float v;
    if (c == 0) v = bw[o * HID + i];
    else        v = sw[(o * HID + i) * NCOEF + (c - 1)] * sc[o * HID + i];
    if (layer) g_W2[t] = v; else g_W1[t] = v;
}

// Normalize prototypes and transpose: PnT[j][k] = protos[k][j] / max(||p_k||, eps)
__global__ void prep_protos(const float* __restrict__ protos) {
    int k = threadIdx.x;  // single block of 256
    float s = 0.f;
    #pragma unroll 4
    for (int j = 0; j < HID; j++) { float v = protos[k * HID + j]; s += v * v; }
    float inv = 1.0f / fmaxf(sqrtf(s), 1e-8f);
    for (int j = 0; j < HID; j++)
        g_PnT[j * NPROTO + k] = protos[k * HID + j] * inv;
}

// ---------------------------------------------------------------------------
// Feature expansion: hs (ROWS x HID, pitch HS_PITCH) -> F (NFEAT x ROWS, k-major)
// Per (row,i): F[i*9+0][r] = silu(x), F[i*9+1..8][r] = cubic B-spline bases.
// Uniform grid: all level-p denominators equal p*h -> use 3 reciprocals.
// ---------------------------------------------------------------------------
__device__ __forceinline__ void compute_features(const float* __restrict__ hs,
                                                 float* __restrict__ F,
                                                 const float* __restrict__ gk,
                                                 int tid) {
    float inv1 = 1.0f / (gk[1] - gk[0]);
    float inv2 = 1.0f / (gk[2] - gk[0]);
    float inv3 = 1.0f / (gk[3] - gk[0]);
    #pragma unroll
    for (int p = tid; p < ROWS * HID; p += THREADS) {
        int r = p & (ROWS - 1);
        int i = p >> 5;
        float xv = hs[r * HS_PITCH + i];
        float sg = 1.0f / (1.0f + __expf(-xv));
        float* Fo = F + (i * 9) * ROWS + r;
        Fo[0] = xv * sg;

        float b[11];
        #pragma unroll
        for (int j = 0; j < 11; j++)
            b[j] = (xv >= gk[j] && xv < gk[j + 1]) ? 1.0f : 0.0f;
        // p = 1
        #pragma unroll
        for (int j = 0; j < 10; j++) {
            float left  = (xv - gk[j]) * inv1;
            float right = (gk[j + 2] - xv) * inv1;
            b[j] = left * b[j] + right * b[j + 1];
        }
        // p = 2
        #pragma unroll
        for (int j = 0; j < 9; j++) {
            float left  = (xv - gk[j]) * inv2;
            float right = (gk[j + 3] - xv) * inv2;
            b[j] = left * b[j] + right * b[j + 1];
        }
        // p = 3
        #pragma unroll
        for (int j = 0; j < 8; j++) {
            float left  = (xv - gk[j]) * inv3;
            float right = (gk[j + 4] - xv) * inv3;
            b[j] = left * b[j] + right * b[j + 1];
        }
        #pragma unroll
        for (int c = 0; c < 8; c++) Fo[(c + 1) * ROWS] = b[c];
    }
}

// ---------------------------------------------------------------------------
// Register-tiled GEMM: acc[4][4] += F(k-major, NFEAT x ROWS) * W(k x HID),
// W streamed from global (L2-resident) in KC-row chunks into smem.
// Thread (rg = tid/32, cg = tid%32) owns rows rg*4..+3, cols cg*4..+3.
// ---------------------------------------------------------------------------
__device__ __forceinline__ void gemm_layer(const float* __restrict__ W,
                                           const float* __restrict__ F,
                                           float* __restrict__ bs,
                                           float acc[4][4], int tid, int nk) {
    int cg = tid & 31, rg = tid >> 5;
    #pragma unroll
    for (int ii = 0; ii < 4; ii++)
        #pragma unroll
        for (int jj = 0; jj < 4; jj++) acc[ii][jj] = 0.f;

    for (int kc = 0; kc < nk; kc += KC) {
        __syncthreads();   // bs reuse guard
        #pragma unroll
        for (int q = 0; q < 4; q++) {
            int v = tid + THREADS * q;         // float4 index over KC*HID/4 = 1024
            int kk = v >> 5, c4 = v & 31;
            float4 w = reinterpret_cast<const float4*>(W + (size_t)kc * HID)[v];
            reinterpret_cast<float4*>(bs + kk * BS_PITCH + c4 * 4)[0] = w;
        }
        __syncthreads();   // bs ready (also guards F readiness on first chunk)
        #pragma unroll
        for (int kk = 0; kk < KC; kk++) {
            float4 a  = reinterpret_cast<const float4*>(F + (kc + kk) * ROWS)[rg];
            float4 bv = reinterpret_cast<const float4*>(bs + kk * BS_PITCH)[cg];
            float av[4] = {a.x, a.y, a.z, a.w};
            float bb[4] = {bv.x, bv.y, bv.z, bv.w};
            #pragma unroll
            for (int ii = 0; ii < 4; ii++)
                #pragma unroll
                for (int jj = 0; jj < 4; jj++)
                    acc[ii][jj] = fmaf(av[ii], bb[jj], acc[ii][jj]);
        }
    }
}

// ---------------------------------------------------------------------------
// Fully fused kernel: x tile -> features -> layer1 -> features -> layer2(emb)
//                     -> emb out + cos-sim argmax vs 256 prototypes
// ---------------------------------------------------------------------------
__global__ void __launch_bounds__(THREADS, 1)
kan_kernel(const float* __restrict__ x, const float* __restrict__ grid,
           float* __restrict__ out_emb, float* __restrict__ out_asn) {
    extern __shared__ float smem[];
    float* F  = smem;                       // NFEAT x ROWS   (k-major)
    float* hs = F + NFEAT * ROWS;           // ROWS x HS_PITCH
    float* bs = hs + ROWS * HS_PITCH;       // KC x BS_PITCH
    float* gk = bs + KC * BS_PITCH;         // 12 grid knots

    int tid = threadIdx.x;
    int row0 = blockIdx.x * ROWS;
    int cg = tid & 31, rg = tid >> 5;

    if (tid < 12) gk[tid] = grid[tid];      // all grid rows identical

    // Load x tile (coalesced float4 reads, scalar smem stores into padded tile)
    #pragma unroll
    for (int q = 0; q < 4; q++) {
        int v = tid + THREADS * q;          // float4 index over ROWS*HID/4 = 1024
        int r = v >> 5, c4 = v & 31;
        float4 xv = reinterpret_cast<const float4*>(x)[(size_t)row0 * (HID / 4) + v];
        float* d = hs + r * HS_PITCH + c4 * 4;
        d[0] = xv.x; d[1] = xv.y; d[2] = xv.z; d[3] = xv.w;
    }
    __syncthreads();

    float acc[4][4];

    // ---- Layer 1 ----
    compute_features(hs, F, gk, tid);
    gemm_layer(g_W1, F, bs, acc, tid, NFEAT);
    __syncthreads();                        // wait: all F/bs reads done
    #pragma unroll
    for (int ii = 0; ii < 4; ii++)
        #pragma unroll
        for (int jj = 0; jj < 4; jj++)
            hs[(rg * 4 + ii) * HS_PITCH + cg * 4 + jj] = acc[ii][jj];
    __syncthreads();

    // ---- Layer 2 ----
    compute_features(hs, F, gk, tid);
    gemm_layer(g_W2, F, bs, acc, tid, NFEAT);
    __syncthreads();                        // all F reads done -> F reusable as esF

    // Write emb to global (coalesced float4), and stash transposed copy in F
    #pragma unroll
    for (int ii = 0; ii < 4; ii++) {
        float4 v = make_float4(acc[ii][0], acc[ii][1], acc[ii][2], acc[ii][3]);
        reinterpret_cast<float4*>(out_emb + (size_t)(row0 + rg * 4 + ii) * HID + cg * 4)[0] = v;
        #pragma unroll
        for (int jj = 0; jj < 4; jj++)
            F[(cg * 4 + jj) * ROWS + (rg * 4 + ii)] = acc[ii][jj];   // esF[j][r]
    }
    // (visibility of esF guaranteed by the post-load __syncthreads in sim GEMM)

    // ---- Cosine-sim argmax: sim = esF^T (32xHID) * PnT (HID x 256), two 128-col passes
    float bestv[4]; int besti[4];
    #pragma unroll
    for (int ii = 0; ii < 4; ii++) { bestv[ii] = -3.4e38f; besti[ii] = 0; }

    #pragma unroll
    for (int pass = 0; pass < 2; pass++) {
        float sacc[4][4];
        #pragma unroll
        for (int ii = 0; ii < 4; ii++)
            #pragma unroll
            for (int jj = 0; jj < 4; jj++) sacc[ii][jj] = 0.f;

        for (int jc = 0; jc < HID; jc += KC) {
            __syncthreads();
            #pragma unroll
            for (int q = 0; q < 4; q++) {
                int v = tid + THREADS * q;
                int kk = v >> 5, c4 = v & 31;
                float4 w = reinterpret_cast<const float4*>(
                    g_PnT + (size_t)(jc + kk) * NPROTO + pass * 128)[c4];
                reinterpret_cast<float4*>(bs + kk * BS_PITCH + c4 * 4)[0] = w;
            }
            __syncthreads();
            #pragma unroll
            for (int kk = 0; kk < KC; kk++) {
                float4 a  = reinterpret_cast<const float4*>(F + (jc + kk) * ROWS)[rg];
                float4 bv = reinterpret_cast<const float4*>(bs + kk * BS_PITCH)[cg];
                float av[4] = {a.x, a.y, a.z, a.w};
                float bb[4] = {bv.x, bv.y, bv.z, bv.w};
                #pragma unroll
                for (int ii = 0; ii < 4; ii++)
                    #pragma unroll
                    for (int jj = 0; jj < 4; jj++)
                        sacc[ii][jj] = fmaf(av[ii], bb[jj], sacc[ii][jj]);
            }
        }
        #pragma unroll
        for (int ii = 0; ii < 4; ii++)
            #pragma unroll
            for (int jj = 0; jj < 4; jj++) {
                int idx = pass * 128 + cg * 4 + jj;    // scanned in ascending order
                if (sacc[ii][jj] > bestv[ii]) { bestv[ii] = sacc[ii][jj]; besti[ii] = idx; }
            }
    }

    // Cross-lane reduction: the 32 lanes of a warp share the same 4 rows (rg const).
    // Tie-break: lower index wins (matches jnp.argmax first-occurrence).
    #pragma unroll
    for (int ii = 0; ii < 4; ii++) {
        float v = bestv[ii]; int bi = besti[ii];
        #pragma unroll
        for (int off = 16; off > 0; off >>= 1) {
            float ov = __shfl_xor_sync(0xffffffffu, v, off);
            int   oi = __shfl_xor_sync(0xffffffffu, bi, off);
            if (ov > v || (ov == v && oi < bi)) { v = ov; bi = oi; }
        }
        if (cg == 0) out_asn[row0 + rg * 4 + ii] = (float)bi;
    }
}

// ---------------------------------------------------------------------------
extern "C" void kernel_launch(void* const* d_in, const int* in_sizes, int n_in,
                              void* d_out, int out_size) {
    const float* x      = (const float*)d_in[0];
    const float* protos = (const float*)d_in[1];
    const float* grid   = (const float*)d_in[2];
    const float* bw1    = (const float*)d_in[3];
    const float* sw1    = (const float*)d_in[4];
    const float* sc1    = (const float*)d_in[5];
    const float* bw2    = (const float*)d_in[6];
    const float* sw2    = (const float*)d_in[7];
    const float* sc2    = (const float*)d_in[8];

    int n = in_sizes[0] / HID;              // number of rows (131072)
    float* out_emb = (float*)d_out;
    float* out_asn = out_emb + (size_t)n * HID;

    prep_weights<<<(2 * NFEAT * HID + 255) / 256, 256>>>(bw1, sw1, sc1, bw2, sw2, sc2);
    prep_protos<<<1, 256>>>(protos);

    size_t smem_bytes = (size_t)SMEM_FLOATS * sizeof(float);   // ~181 KB
    cudaFuncSetAttribute(kan_kernel, cudaFuncAttributeMaxDynamicSharedMemorySize,
                         (int)smem_bytes);
    kan_kernel<<<n / ROWS, THREADS, smem_bytes>>>(x, grid, out_emb, out_asn);
}

// round 2
// speedup vs baseline: 1.0488x; 1.0488x over previous
#include <cuda_runtime.h>
#include <math.h>

#define HID     128
#define NCOEF   8
#define NFEAT   (HID * 9)        // 1152 expanded features per row
#define NPROTO  256
#define ROWS    32               // rows per CTA
#define THREADS 256
#define KC      32               // k-chunk for GEMM
#define HS_PITCH 129             // padded pitch for h / x tile (conflict-free scalar access)
#define BS_PITCH 132             // padded pitch for B chunk (16B aligned rows, conflict-free vec access)

#define SMEM_FLOATS (NFEAT*ROWS + ROWS*HS_PITCH + KC*BS_PITCH + 16)

// Device scratch (no allocations allowed)
__device__ float g_W1[NFEAT * HID];
__device__ float g_W2[NFEAT * HID];
__device__ float g_PnT[HID * NPROTO];   // transposed, row-normalized prototypes

// ---------------------------------------------------------------------------
// Prep: build combined KAN weights  W[k=i*9+c][o]
//   c==0   -> base_w[o][i]
//   c>=1   -> spline_w[o][i][c-1] * scaler[o][i]
// ---------------------------------------------------------------------------
__global__ void prep_weights(const float* __restrict__ bw1, const float* __restrict__ sw1,
                             const float* __restrict__ sc1,
                             const float* __restrict__ bw2, const float* __restrict__ sw2,
                             const float* __restrict__ sc2) {
    int idx = blockIdx.x * blockDim.x + threadIdx.x;
    const int total = NFEAT * HID;
    if (idx >= 2 * total) return;
    int layer = idx / total;
    int t = idx - layer * total;
    int k = t / HID;
    int o = t - k * HID;
    int i = k / 9;
    int c = k - i * 9;
    const float* bw = layer ? bw2 : bw1;
    const float* sw = layer ? sw2 : sw1;
    const float* sc = layer ? sc2 : sc1;
    float v;
    if (c == 0) v = bw[o * HID + i];
    else        v = sw[(o * HID + i) * NCOEF + (c - 1)] * sc[o * HID + i];
    if (layer) g_W2[t] = v; else g_W1[t] = v;
}

// Normalize prototypes and transpose: PnT[j][k] = protos[k][j] / max(||p_k||, eps)
__global__ void prep_protos(const float* __restrict__ protos) {
    int k = threadIdx.x;  // single block of 256
    float s = 0.f;
    #pragma unroll 4
    for (int j = 0; j < HID; j++) { float v = protos[k * HID + j]; s += v * v; }
    float inv = 1.0f / fmaxf(sqrtf(s), 1e-8f);
    for (int j = 0; j < HID; j++)
        g_PnT[j * NPROTO + k] = protos[k * HID + j] * inv;
}

// ---------------------------------------------------------------------------
// Feature expansion: hs (ROWS x HID, pitch HS_PITCH) -> F (NFEAT x ROWS, k-major)
// Per (row,i): F[i*9+0][r] = silu(x), F[i*9+1..8][r] = cubic B-spline bases.
// Uniform grid: all level-p denominators equal p*h -> use 3 reciprocals.
// ---------------------------------------------------------------------------
__device__ __forceinline__ void compute_features(const float* __restrict__ hs,
                                                 float* __restrict__ F,
                                                 const float* __restrict__ gk,
                                                 int tid) {
    float inv1 = 1.0f / (gk[1] - gk[0]);
    float inv2 = 1.0f / (gk[2] - gk[0]);
    float inv3 = 1.0f / (gk[3] - gk[0]);
    #pragma unroll
    for (int p = tid; p < ROWS * HID; p += THREADS) {
        int r = p & (ROWS - 1);
        int i = p >> 5;
        float xv = hs[r * HS_PITCH + i];
        float sg = 1.0f / (1.0f + __expf(-xv));
        float* Fo = F + (i * 9) * ROWS + r;
        Fo[0] = xv * sg;

        float b[11];
        #pragma unroll
        for (int j = 0; j < 11; j++)
            b[j] = (xv >= gk[j] && xv < gk[j + 1]) ? 1.0f : 0.0f;
        // p = 1
        #pragma unroll
        for (int j = 0; j < 10; j++) {
            float left  = (xv - gk[j]) * inv1;
            float right = (gk[j + 2] - xv) * inv1;
            b[j] = left * b[j] + right * b[j + 1];
        }
        // p = 2
        #pragma unroll
        for (int j = 0; j < 9; j++) {
            float left  = (xv - gk[j]) * inv2;
            float right = (gk[j + 3] - xv) * inv2;
            b[j] = left * b[j] + right * b[j + 1];
        }
        // p = 3
        #pragma unroll
        for (int j = 0; j < 8; j++) {
            float left  = (xv - gk[j]) * inv3;
            float right = (gk[j + 4] - xv) * inv3;
            b[j] = left * b[j] + right * b[j + 1];
        }
        #pragma unroll
        for (int c = 0; c < 8; c++) Fo[(c + 1) * ROWS] = b[c];
    }
}

// ---------------------------------------------------------------------------
// Register-tiled GEMM: acc[4][4] += F(k-major, NFEAT x ROWS) * W(k x HID),
// W streamed from global (L2-resident) in KC-row chunks into smem.
// Thread (rg = tid/32, cg = tid%32) owns rows rg*4..+3, cols cg*4..+3.
// ---------------------------------------------------------------------------
__device__ __forceinline__ void gemm_layer(const float* __restrict__ W,
                                           const float* __restrict__ F,
                                           float* __restrict__ bs,
                                           float acc[4][4], int tid, int nk) {
    int cg = tid & 31, rg = tid >> 5;
    #pragma unroll
    for (int ii = 0; ii < 4; ii++)
        #pragma unroll
        for (int jj = 0; jj < 4; jj++) acc[ii][jj] = 0.f;

    for (int kc = 0; kc < nk; kc += KC) {
        __syncthreads();   // bs reuse guard
        #pragma unroll
        for (int q = 0; q < 4; q++) {
            int v = tid + THREADS * q;         // float4 index over KC*HID/4 = 1024
            int kk = v >> 5, c4 = v & 31;
            float4 w = reinterpret_cast<const float4*>(W + (size_t)kc * HID)[v];
            reinterpret_cast<float4*>(bs + kk * BS_PITCH + c4 * 4)[0] = w;
        }
        __syncthreads();   // bs ready (also guards F readiness on first chunk)
        #pragma unroll
        for (int kk = 0; kk < KC; kk++) {
            float4 a  = reinterpret_cast<const float4*>(F + (kc + kk) * ROWS)[rg];
            float4 bv = reinterpret_cast<const float4*>(bs + kk * BS_PITCH)[cg];
            float av[4] = {a.x, a.y, a.z, a.w};
            float bb[4] = {bv.x, bv.y, bv.z, bv.w};
            #pragma unroll
            for (int ii = 0; ii < 4; ii++)
                #pragma unroll
                for (int jj = 0; jj < 4; jj++)
                    acc[ii][jj] = fmaf(av[ii], bb[jj], acc[ii][jj]);
        }
    }
}

// ---------------------------------------------------------------------------
// Fully fused kernel: x tile -> features -> layer1 -> features -> layer2(emb)
//                     -> emb out + cos-sim argmax vs 256 prototypes
// ---------------------------------------------------------------------------
__global__ void __launch_bounds__(THREADS, 1)
kan_kernel(const float* __restrict__ x, const float* __restrict__ grid,
           float* __restrict__ out_emb, float* __restrict__ out_asn) {
    extern __shared__ float smem[];
    float* F  = smem;                       // NFEAT x ROWS   (k-major)
    float* hs = F + NFEAT * ROWS;           // ROWS x HS_PITCH
    float* bs = hs + ROWS * HS_PITCH;       // KC x BS_PITCH
    float* gk = bs + KC * BS_PITCH;         // 12 grid knots

    int tid = threadIdx.x;
    int row0 = blockIdx.x * ROWS;
    int cg = tid & 31, rg = tid >> 5;

    if (tid < 12) gk[tid] = grid[tid];      // all grid rows identical

    // Load x tile (coalesced float4 reads, scalar smem stores into padded tile)
    #pragma unroll
    for (int q = 0; q < 4; q++) {
        int v = tid + THREADS * q;          // float4 index over ROWS*HID/4 = 1024
        int r = v >> 5, c4 = v & 31;
        float4 xv = reinterpret_cast<const float4*>(x)[(size_t)row0 * (HID / 4) + v];
        float* d = hs + r * HS_PITCH + c4 * 4;
        d[0] = xv.x; d[1] = xv.y; d[2] = xv.z; d[3] = xv.w;
    }
    __syncthreads();

    float acc[4][4];

    // ---- Layer 1 ----
    compute_features(hs, F, gk, tid);
    gemm_layer(g_W1, F, bs, acc, tid, NFEAT);
    __syncthreads();                        // wait: all F/bs reads done
    #pragma unroll
    for (int ii = 0; ii < 4; ii++)
        #pragma unroll
        for (int jj = 0; jj < 4; jj++)
            hs[(rg * 4 + ii) * HS_PITCH + cg * 4 + jj] = acc[ii][jj];
    __syncthreads();

    // ---- Layer 2 ----
    compute_features(hs, F, gk, tid);
    gemm_layer(g_W2, F, bs, acc, tid, NFEAT);
    __syncthreads();                        // all F reads done -> F reusable as esF

    // Write emb to global (coalesced float4), and stash transposed copy in F
    #pragma unroll
    for (int ii = 0; ii < 4; ii++) {
        float4 v = make_float4(acc[ii][0], acc[ii][1], acc[ii][2], acc[ii][3]);
        reinterpret_cast<float4*>(out_emb + (size_t)(row0 + rg * 4 + ii) * HID + cg * 4)[0] = v;
        #pragma unroll
        for (int jj = 0; jj < 4; jj++)
            F[(cg * 4 + jj) * ROWS + (rg * 4 + ii)] = acc[ii][jj];   // esF[j][r]
    }
    // (visibility of esF guaranteed by the post-load __syncthreads in sim GEMM)

    // ---- Cosine-sim argmax: sim = esF^T (32xHID) * PnT (HID x 256), two 128-col passes
    float bestv[4]; int besti[4];
    #pragma unroll
    for (int ii = 0; ii < 4; ii++) { bestv[ii] = -3.4e38f; besti[ii] = 0; }

    #pragma unroll
    for (int pass = 0; pass < 2; pass++) {
        float sacc[4][4];
        #pragma unroll
        for (int ii = 0; ii < 4; ii++)
            #pragma unroll
            for (int jj = 0; jj < 4; jj++) sacc[ii][jj] = 0.f;

        for (int jc = 0; jc < HID; jc += KC) {
            __syncthreads();
            #pragma unroll
            for (int q = 0; q < 4; q++) {
                int v = tid + THREADS * q;
                int kk = v >> 5, c4 = v & 31;
                float4 w = reinterpret_cast<const float4*>(
                    g_PnT + (size_t)(jc + kk) * NPROTO + pass * 128)[c4];
                reinterpret_cast<float4*>(bs + kk * BS_PITCH + c4 * 4)[0] = w;
            }
            __syncthreads();
            #pragma unroll
            for (int kk = 0; kk < KC; kk++) {
                float4 a  = reinterpret_cast<const float4*>(F + (jc + kk) * ROWS)[rg];
                float4 bv = reinterpret_cast<const float4*>(bs + kk * BS_PITCH)[cg];
                float av[4] = {a.x, a.y, a.z, a.w};
                float bb[4] = {bv.x, bv.y, bv.z, bv.w};
                #pragma unroll
                for (int ii = 0; ii < 4; ii++)
                    #pragma unroll
                    for (int jj = 0; jj < 4; jj++)
                        sacc[ii][jj] = fmaf(av[ii], bb[jj], sacc[ii][jj]);
            }
        }
        #pragma unroll
        for (int ii = 0; ii < 4; ii++)
            #pragma unroll
            for (int jj = 0; jj < 4; jj++) {
                int idx = pass * 128 + cg * 4 + jj;    // scanned in ascending order
                if (sacc[ii][jj] > bestv[ii]) { bestv[ii] = sacc[ii][jj]; besti[ii] = idx; }
            }
    }

    // Cross-lane reduction: the 32 lanes of a warp share the same 4 rows (rg const).
    // Tie-break: lower index wins (matches jnp.argmax first-occurrence).
    #pragma unroll
    for (int ii = 0; ii < 4; ii++) {
        float v = bestv[ii]; int bi = besti[ii];
        #pragma unroll
        for (int off = 16; off > 0; off >>= 1) {
            float ov = __shfl_xor_sync(0xffffffffu, v, off);
            int   oi = __shfl_xor_sync(0xffffffffu, bi, off);
            if (ov > v || (ov == v && oi < bi)) { v = ov; bi = oi; }
        }
        if (cg == 0) out_asn[row0 + rg * 4 + ii] = (float)bi;
    }
}

// ---------------------------------------------------------------------------
extern "C" void kernel_launch(void* const* d_in, const int* in_sizes, int n_in,
                              void* d_out, int out_size) {
    const float* x      = (const float*)d_in[0];
    const float* protos = (const float*)d_in[1];
    const float* grid   = (const float*)d_in[2];
    const float* bw1    = (const float*)d_in[3];
    const float* sw1    = (const float*)d_in[4];
    const float* sc1    = (const float*)d_in[5];
    const float* bw2    = (const float*)d_in[6];
    const float* sw2    = (const float*)d_in[7];
    const float* sc2    = (const float*)d_in[8];

    int n = in_sizes[0] / HID;              // number of rows (131072)
    float* out_emb = (float*)d_out;
    float* out_asn = out_emb + (size_t)n * HID;

    prep_weights<<<(2 * NFEAT * HID + 255) / 256, 256>>>(bw1, sw1, sc1, bw2, sw2, sc2);
    prep_protos<<<1, 256>>>(protos);

    size_t smem_bytes = (size_t)SMEM_FLOATS * sizeof(float);   // ~181 KB
    cudaFuncSetAttribute(kan_kernel, cudaFuncAttributeMaxDynamicSharedMemorySize,
                         (int)smem_bytes);
    kan_kernel<<<n / ROWS, THREADS, smem_bytes>>>(x, grid, out_emb, out_asn);
}

// round 10
// speedup vs baseline: 1.7039x; 1.6246x over previous
#include <cuda_runtime.h>
#include <cuda_bf16.h>
#include <cstdint>
#include <math.h>

#define HID     128
#define KTOT    1152
#define THREADS 256

// ---- smem byte offsets ----
#define SM_HS   0                 // 128 x 132 floats = 67584 B (x/h/emb tile; later sim bs)
#define SM_A    67584             // 2 stages x 24576 B (3 bf16 comps x 8KB); later esT (67584 B)
#define SM_B    116736            // 2 stages x 24576 B
#define SMEM_BYTES 169984

// ---- device scratch (no allocations allowed) ----
// W fragment layout: [layer][chunk(36)][comp(3)][4096 bf16]
__device__ __align__(16) __nv_bfloat16 g_WB[2 * 36 * 3 * 4096];
// normalized prototypes, k-major: PnT[k][proto]  (128 x 256 f32)
__device__ __align__(16) float g_PnT[HID * 256];

__device__ __forceinline__ uint32_t smem_u32(const void* p) {
    uint32_t a;
    asm("{ .reg .u64 t; cvta.to.shared.u64 t, %1; cvt.u32.u64 %0, t; }" : "=r"(a) : "l"(p));
    return a;
}
__device__ __forceinline__ void cp16(uint32_t dst, const void* src) {
    asm volatile("cp.async.cg.shared.global [%0], [%1], 16;" :: "r"(dst), "l"(src));
}
__device__ __forceinline__ void mma16(float* d, uint4 a, uint2 b) {
    asm volatile(
        "mma.sync.aligned.m16n8k16.row.col.f32.bf16.bf16.f32 "
        "{%0,%1,%2,%3},{%4,%5,%6,%7},{%8,%9},{%0,%1,%2,%3};"
        : "+f"(d[0]), "+f"(d[1]), "+f"(d[2]), "+f"(d[3])
        : "r"(a.x), "r"(a.y), "r"(a.z), "r"(a.w), "r"(b.x), "r"(b.y));
}
// 3-way bf16 split: s[0]+s[1]+s[2] == v to ~2^-25 relative
__device__ __forceinline__ void split3(float v, uint16_t* s) {
    __nv_bfloat16 b1 = __float2bfloat16(v);
    float r1 = v - __bfloat162float(b1);
    __nv_bfloat16 b2 = __float2bfloat16(r1);
    float r2 = r1 - __bfloat162float(b2);
    __nv_bfloat16 b3 = __float2bfloat16(r2);
    s[0] = *(uint16_t*)&b1; s[1] = *(uint16_t*)&b2; s[2] = *(uint16_t*)&b3;
}

// cubic B-spline: 8 basis values (uniform knots gk[0..11])
__device__ __forceinline__ void spline8(float xv, const float* gk,
                                        float i1, float i2, float i3, float* b) {
    float t[11];
    #pragma unroll
    for (int j = 0; j < 11; j++)
        t[j] = (xv >= gk[j] && xv < gk[j + 1]) ? 1.0f : 0.0f;
    #pragma unroll
    for (int j = 0; j < 10; j++)
        t[j] = (xv - gk[j]) * i1 * t[j] + (gk[j + 2] - xv) * i1 * t[j + 1];
    #pragma unroll
    for (int j = 0; j < 9; j++)
        t[j] = (xv - gk[j]) * i2 * t[j] + (gk[j + 3] - xv) * i2 * t[j + 1];
    #pragma unroll
    for (int j = 0; j < 8; j++)
        b[j] = (xv - gk[j]) * i3 * t[j] + (gk[j + 4] - xv) * i3 * t[j + 1];
}

// ---------------------------------------------------------------------------
// Prep: combined KAN weights in mma B-fragment layout, bf16x3 split.
//   k<128 -> base_w[o][k]; else m=k-128 -> spline_w[o][m>>3][m&7]*scaler[o][m>>3]
// ---------------------------------------------------------------------------
__global__ void prep_w(const float* __restrict__ bw1, const float* __restrict__ sw1,
                       const float* __restrict__ sc1,
                       const float* __restrict__ bw2, const float* __restrict__ sw2,
                       const float* __restrict__ sc2) {
    int idx = blockIdx.x * blockDim.x + threadIdx.x;
    const int per = HID * KTOT;
    if (idx >= 2 * per) return;
    int l = idx / per, t = idx - l * per;
    int o = t / KTOT, k = t - o * KTOT;
    const float* bw = l ? bw2 : bw1;
    const float* sw = l ? sw2 : sw1;
    const float* sc = l ? sc2 : sc1;
    float v;
    if (k < HID) v = bw[o * HID + k];
    else { int m = k - HID; int i = m >> 3; int cc = m & 7; v = sw[(o * HID + i) * 8 + cc] * sc[o * HID + i]; }
    uint16_t s[3];
    split3(v, s);
    int chunk = k >> 5, kk = k & 31, ks = kk >> 4, kb = kk & 15;
    int reg = kb >> 3, k8 = kb & 7, half = kb & 1;
    int wn = o >> 6, nt = (o >> 3) & 7, n8 = o & 7;
    int lane = n8 * 4 + (k8 >> 1);
    int u = (((wn * 2 + ks) * 8 + nt) * 32 + lane) * 2 + reg;
    size_t base = ((size_t)(l * 36 + chunk)) * 3 * 4096;
    #pragma unroll
    for (int c = 0; c < 3; c++)
        *(uint16_t*)&g_WB[base + c * 4096 + u * 2 + half] = s[c];
}

// Normalize prototypes, transposed k-major (round-1 style)
__global__ void prep_protos(const float* __restrict__ p) {
    int n = threadIdx.x;  // 256 threads, one proto each
    float s = 0.f;
    for (int j = 0; j < HID; j++) { float v = p[n * HID + j]; s += v * v; }
    float inv = 1.0f / fmaxf(sqrtf(s), 1e-8f);
    for (int j = 0; j < HID; j++)
        g_PnT[j * 256 + n] = p[n * HID + j] * inv;
}

// ---------------------------------------------------------------------------
// A-fragment generation into smem (3 bf16 comps, paired u32 stores)
// ---------------------------------------------------------------------------
__device__ __forceinline__ void genA(int c, uint32_t* A, const float* hs,
                                     const float* gk, float i1, float i2, float i3, int tid) {
    int r = tid & 127, half = tid >> 7;
    int ms = r >> 5, rr = r & 31, t = rr >> 4, fr = rr & 15;
    int regbase  = (fr >= 8) ? 1 : 0;
    int lanebase = (fr & 7) * 4;
    int fragbase = (ms * 2 + t) * 2;
    if (c < 4) {                                    // silu block
        const float* src = hs + r * 132 + c * 32 + half * 16;
        #pragma unroll
        for (int j = 0; j < 8; j++) {
            int kk = half * 16 + j * 2;
            float v0 = src[j * 2], v1 = src[j * 2 + 1];
            float sg0 = 1.0f / (1.0f + __expf(-v0));
            float sg1 = 1.0f / (1.0f + __expf(-v1));
            v0 = v0 * sg0; v1 = v1 * sg1;
            uint16_t s0[3], s1[3];
            split3(v0, s0); split3(v1, s1);
            int ks = kk >> 4, kb = kk & 15;
            int reg = regbase + ((kb >= 8) ? 2 : 0);
            int lane = lanebase + ((kb & 7) >> 1);
            int u = ((fragbase + ks) * 32 + lane) * 4 + reg;
            #pragma unroll
            for (int cc = 0; cc < 3; cc++)
                A[cc * 2048 + u] = (uint32_t)s0[cc] | ((uint32_t)s1[cc] << 16);
        }
    } else {                                        // spline block: 4 channels
        int m = c - 4;
        #pragma unroll
        for (int pp = 0; pp < 2; pp++) {
            int ch = half + 2 * pp;
            float xv = hs[r * 132 + m * 4 + ch];
            float b[8];
            spline8(xv, gk, i1, i2, i3, b);
            #pragma unroll
            for (int j = 0; j < 4; j++) {
                int kk = ch * 8 + j * 2;
                uint16_t s0[3], s1[3];
                split3(b[j * 2], s0); split3(b[j * 2 + 1], s1);
                int ks = kk >> 4, kb = kk & 15;
                int reg = regbase + ((kb >= 8) ? 2 : 0);
                int lane = lanebase + ((kb & 7) >> 1);
                int u = ((fragbase + ks) * 32 + lane) * 4 + reg;
                #pragma unroll
                for (int cc = 0; cc < 3; cc++)
                    A[cc * 2048 + u] = (uint32_t)s0[cc] | ((uint32_t)s1[cc] << 16);
            }
        }
    }
}

// one K-chunk into a FRESH sub-accumulator (caller zeroes), 6-product bf16x3
__device__ __forceinline__ void mma_chunk(float sub[2][8][4], const uint32_t* As, const uint32_t* Bs,
                                          int ms, int wn, int lane) {
    #pragma unroll
    for (int ks = 0; ks < 2; ks++) {
        uint4 a[3][2];
        #pragma unroll
        for (int cc = 0; cc < 3; cc++)
            #pragma unroll
            for (int t = 0; t < 2; t++)
                a[cc][t] = *(const uint4*)(As + cc * 2048 + (((ms * 2 + t) * 2 + ks) * 32 + lane) * 4);
        #pragma unroll
        for (int nt = 0; nt < 8; nt++) {
            uint2 b0 = *(const uint2*)(Bs +        (((wn * 2 + ks) * 8 + nt) * 32 + lane) * 2);
            uint2 b1 = *(const uint2*)(Bs + 2048 + (((wn * 2 + ks) * 8 + nt) * 32 + lane) * 2);
            uint2 b2 = *(const uint2*)(Bs + 4096 + (((wn * 2 + ks) * 8 + nt) * 32 + lane) * 2);
            #pragma unroll
            for (int t = 0; t < 2; t++) {
                mma16(sub[t][nt], a[2][t], b0);   // a3*b1  (small terms first)
                mma16(sub[t][nt], a[1][t], b1);   // a2*b2
                mma16(sub[t][nt], a[0][t], b2);   // a1*b3
                mma16(sub[t][nt], a[1][t], b0);   // a2*b1
                mma16(sub[t][nt], a[0][t], b1);   // a1*b2
                mma16(sub[t][nt], a[0][t], b0);   // a1*b1
            }
        }
    }
}

// pipelined layer GEMM: cp.async B(c+1) + genA(c+1) overlap mma(c);
// per-chunk sub-accumulator merged into acc (kills accumulation-order noise)
__device__ __forceinline__ void run_gemm(float acc[2][8][4], const __nv_bfloat16* gsrc,
                                         char* smc, uint32_t sb, const float* hs, const float* gk,
                                         float i1, float i2, float i3,
                                         int tid, int ms, int wn, int lane) {
    {   // prologue: fill stage 0
        uint32_t bd = sb + SM_B;
        const char* src = (const char*)gsrc;
        #pragma unroll
        for (int i = 0; i < 6; i++) cp16(bd + tid * 16 + i * 4096, src + tid * 16 + i * 4096);
        asm volatile("cp.async.commit_group;");
        genA(0, (uint32_t*)(smc + SM_A), hs, gk, i1, i2, i3, tid);
        asm volatile("cp.async.wait_group 0;" ::: "memory");
        __syncthreads();
    }
    for (int c = 0; c < 36; c++) {
        int s = c & 1;
        if (c + 1 < 36) {
            uint32_t bd = sb + SM_B + (s ^ 1) * 24576;
            const char* src = (const char*)(gsrc + (size_t)(c + 1) * 12288);
            #pragma unroll
            for (int i = 0; i < 6; i++) cp16(bd + tid * 16 + i * 4096, src + tid * 16 + i * 4096);
            asm volatile("cp.async.commit_group;");
            genA(c + 1, (uint32_t*)(smc + SM_A + (s ^ 1) * 24576), hs, gk, i1, i2, i3, tid);
        }
        float sub[2][8][4];
        #pragma unroll
        for (int t = 0; t < 2; t++)
            #pragma unroll
            for (int nt = 0; nt < 8; nt++)
                #pragma unroll
                for (int rg = 0; rg < 4; rg++) sub[t][nt][rg] = 0.f;
        mma_chunk(sub, (const uint32_t*)(smc + SM_A + s * 24576),
                       (const uint32_t*)(smc + SM_B + s * 24576), ms, wn, lane);
        #pragma unroll
        for (int t = 0; t < 2; t++)
            #pragma unroll
            for (int nt = 0; nt < 8; nt++)
                #pragma unroll
                for (int rg = 0; rg < 4; rg++) acc[t][nt][rg] += sub[t][nt][rg];
        if (c + 1 < 36) asm volatile("cp.async.wait_group 0;" ::: "memory");
        __syncthreads();
    }
}

// ---------------------------------------------------------------------------
// Fused kernel: x -> KAN layer1 -> layer2 (emb out) -> scalar-fp32 sim argmax
// ---------------------------------------------------------------------------
__global__ void __launch_bounds__(THREADS, 1)
kan_mma(const float* __restrict__ x, const float* __restrict__ grid,
        float* __restrict__ out_emb, float* __restrict__ out_asn) {
    extern __shared__ char smc[];
    uint32_t sb = smem_u32(smc);
    float* hs  = (float*)(smc + SM_HS);
    float* esT = (float*)(smc + SM_A);     // emb transposed [k][r], after layers
    int tid = threadIdx.x, lane = tid & 31, wid = tid >> 5;
    int ms = wid & 3, wn = wid >> 2;
    int row0 = blockIdx.x * 128;

    // load x tile 128x128 (coalesced float4)
    #pragma unroll
    for (int q = 0; q < 16; q++) {
        int v = tid + THREADS * q;
        int r = v >> 5, c4 = v & 31;
        float4 xv = ((const float4*)x)[(size_t)row0 * 32 + v];
        *(float4*)(hs + r * 132 + c4 * 4) = xv;
    }
    float gk[12];
    #pragma unroll
    for (int j = 0; j < 12; j++) gk[j] = grid[j];   // all grid rows identical
    float i1 = 1.0f / (gk[1] - gk[0]);
    float i2 = 1.0f / (gk[2] - gk[0]);
    float i3 = 1.0f / (gk[3] - gk[0]);
    __syncthreads();

    float acc[2][8][4];

    // ---- two KAN layers ----
    for (int layer = 0; layer < 2; layer++) {
        #pragma unroll
        for (int t = 0; t < 2; t++)
            #pragma unroll
            for (int nt = 0; nt < 8; nt++)
                #pragma unroll
                for (int rg = 0; rg < 4; rg++) acc[t][nt][rg] = 0.f;

        run_gemm(acc, g_WB + (size_t)layer * 36 * 12288,
                 smc, sb, hs, gk, i1, i2, i3, tid, ms, wn, lane);

        // epilogue: acc -> hs (m16n8 C layout); layer 2 also -> esT transposed
        #pragma unroll
        for (int t = 0; t < 2; t++)
            #pragma unroll
            for (int nt = 0; nt < 8; nt++) {
                int row = ms * 32 + t * 16 + (lane >> 2);
                int col = wn * 64 + nt * 8 + 2 * (lane & 3);
                *(float2*)(hs + row * 132 + col)       = make_float2(acc[t][nt][0], acc[t][nt][1]);
                *(float2*)(hs + (row + 8) * 132 + col) = make_float2(acc[t][nt][2], acc[t][nt][3]);
                if (layer == 1) {
                    esT[col * 132 + row]             = acc[t][nt][0];
                    esT[(col + 1) * 132 + row]       = acc[t][nt][1];
                    esT[col * 132 + row + 8]         = acc[t][nt][2];
                    esT[(col + 1) * 132 + row + 8]   = acc[t][nt][3];
                }
            }
        __syncthreads();
    }

    // emb out (coalesced float4 from hs)
    #pragma unroll
    for (int q = 0; q < 16; q++) {
        int v = tid + THREADS * q;
        int r = v >> 5, c4 = v & 31;
        float4 e = *(const float4*)(hs + r * 132 + c4 * 4);
        ((float4*)out_emb)[(size_t)row0 * 32 + v] = e;
    }
    __syncthreads();   // hs reads done -> reuse region as bs

    // ---- scalar fp32 cosine-sim + argmax (round-1-proven structure) ----
    float* bs = (float*)(smc + SM_HS);      // 32 x 132 floats per chunk
    int cg = lane, rg = wid;                // thread owns rows rg*4..+3 (per rgrp), cols cg*4..+3
    float bestv[4][4]; int besti[4][4];
    #pragma unroll
    for (int g = 0; g < 4; g++)
        #pragma unroll
        for (int ii = 0; ii < 4; ii++) { bestv[g][ii] = -3.4e38f; besti[g][ii] = 0; }

    #pragma unroll
    for (int pass = 0; pass < 2; pass++) {
        float sacc[4][4][4];
        #pragma unroll
        for (int g = 0; g < 4; g++)
            #pragma unroll
            for (int ii = 0; ii < 4; ii++)
                #pragma unroll
                for (int jj = 0; jj < 4; jj++) sacc[g][ii][jj] = 0.f;

        for (int kc = 0; kc < HID; kc += 32) {
            __syncthreads();   // bs reuse guard
            #pragma unroll
            for (int q = 0; q < 4; q++) {
                int v = tid + THREADS * q;      // float4 idx over 32*128/4 = 1024
                int kk = v >> 5, c4 = v & 31;
                float4 w = *(const float4*)(g_PnT + (size_t)(kc + kk) * 256 + pass * 128 + c4 * 4);
                *(float4*)(bs + kk * 132 + c4 * 4) = w;
            }
            __syncthreads();
            #pragma unroll 8
            for (int kk = 0; kk < 32; kk++) {
                float4 bv = *(const float4*)(bs + kk * 132 + cg * 4);
                float bb[4] = {bv.x, bv.y, bv.z, bv.w};
                #pragma unroll
                for (int g = 0; g < 4; g++) {
                    float4 av = *(const float4*)(esT + (kc + kk) * 132 + g * 32 + rg * 4);
                    float aa[4] = {av.x, av.y, av.z, av.w};
                    #pragma unroll
                    for (int ii = 0; ii < 4; ii++)
                        #pragma unroll
                        for (int jj = 0; jj < 4; jj++)
                            sacc[g][ii][jj] = fmaf(aa[ii], bb[jj], sacc[g][ii][jj]);
                }
            }
        }
        #pragma unroll
        for (int g = 0; g < 4; g++)
            #pragma unroll
            for (int ii = 0; ii < 4; ii++)
                #pragma unroll
                for (int jj = 0; jj < 4; jj++) {
                    int idx = pass * 128 + cg * 4 + jj;   // ascending scan order
                    if (sacc[g][ii][jj] > bestv[g][ii]) { bestv[g][ii] = sacc[g][ii][jj]; besti[g][ii] = idx; }
                }
    }

    // cross-lane reduce (lanes share rows); lower index wins ties
    #pragma unroll
    for (int g = 0; g < 4; g++)
        #pragma unroll
        for (int ii = 0; ii < 4; ii++) {
            float v = bestv[g][ii]; int bi = besti[g][ii];
            #pragma unroll
            for (int off = 16; off > 0; off >>= 1) {
                float ov = __shfl_xor_sync(0xffffffffu, v, off);
                int   oi = __shfl_xor_sync(0xffffffffu, bi, off);
                if (ov > v || (ov == v && oi < bi)) { v = ov; bi = oi; }
            }
            if (cg == 0) out_asn[row0 + g * 32 + rg * 4 + ii] = (float)bi;
        }
}

// ---------------------------------------------------------------------------
extern "C" void kernel_launch(void* const* d_in, const int* in_sizes, int n_in,
                              void* d_out, int out_size) {
    const float* x      = (const float*)d_in[0];
    const float* protos = (const float*)d_in[1];
    const float* grid   = (const float*)d_in[2];
    const float* bw1    = (const float*)d_in[3];
    const float* sw1    = (const float*)d_in[4];
    const float* sc1    = (const float*)d_in[5];
    const float* bw2    = (const float*)d_in[6];
    const float* sw2    = (const float*)d_in[7];
    const float* sc2    = (const float*)d_in[8];

    int n = in_sizes[0] / HID;
    float* out_emb = (float*)d_out;
    float* out_asn = out_emb + (size_t)n * HID;

    prep_w<<<(2 * HID * KTOT + 255) / 256, 256>>>(bw1, sw1, sc1, bw2, sw2, sc2);
    prep_protos<<<1, 256>>>(protos);

    cudaFuncSetAttribute(kan_mma, cudaFuncAttributeMaxDynamicSharedMemorySize, SMEM_BYTES);
    kan_mma<<<n / 128, THREADS, SMEM_BYTES>>>(x, grid, out_emb, out_asn);
}

// round 14
// speedup vs baseline: 2.7049x; 1.5874x over previous
#include <cuda_runtime.h>
#include <cuda_fp16.h>
#include <cstdint>
#include <math.h>

#define HID     128
#define KTOT    1152
#define THREADS 256

// ---- smem byte offsets ----
#define SM_HS   0                 // 128 x 132 floats = 67584 B (x/h/emb tile; later argmax red)
#define SM_A    67584             // 2 stages x 16384 B (2 fp16 comps x 8KB)
#define SM_B    100352            // 2 stages x 16384 B
#define SMEM_BYTES 133120

// ---- device scratch (no allocations allowed) ----
// W fragment layout: [layer][chunk(36)][comp(2)][4096 fp16]
__device__ __align__(16) __half g_WB[2 * 36 * 2 * 4096];
// protos fragment layout: [pass(2)][chunk(4)][comp(2)][4096 fp16]
__device__ __align__(16) __half g_PB[2 * 4 * 2 * 4096];

__device__ __forceinline__ uint32_t smem_u32(const void* p) {
    uint32_t a;
    asm("{ .reg .u64 t; cvta.to.shared.u64 t, %1; cvt.u32.u64 %0, t; }" : "=r"(a) : "l"(p));
    return a;
}
__device__ __forceinline__ void cp16(uint32_t dst, const void* src) {
    asm volatile("cp.async.cg.shared.global [%0], [%1], 16;" :: "r"(dst), "l"(src));
}
__device__ __forceinline__ void mma16(float* d, uint4 a, uint2 b) {
    asm volatile(
        "mma.sync.aligned.m16n8k16.row.col.f32.f16.f16.f32 "
        "{%0,%1,%2,%3},{%4,%5,%6,%7},{%8,%9},{%0,%1,%2,%3};"
        : "+f"(d[0]), "+f"(d[1]), "+f"(d[2]), "+f"(d[3])
        : "r"(a.x), "r"(a.y), "r"(a.z), "r"(a.w), "r"(b.x), "r"(b.y));
}
// 2-way fp16 split (scalar): v = s0 + s1 + O(2^-22 v)
__device__ __forceinline__ void split2(float v, __half* s) {
    __half a1 = __float2half_rn(v);
    float r = v - __half2float(a1);
    s[0] = a1; s[1] = __float2half_rn(r);
}
// packed pair split: returns comp0/comp1 as u32 (2 fp16 each)
__device__ __forceinline__ void split2x2(float v0, float v1, uint32_t* c) {
    __half2 h1 = __floats2half2_rn(v0, v1);
    float2 f1 = __half22float2(h1);
    __half2 h2 = __floats2half2_rn(v0 - f1.x, v1 - f1.y);
    c[0] = *(uint32_t*)&h1; c[1] = *(uint32_t*)&h2;
}

// cubic B-spline: 8 basis values (uniform knots gk[0..11])
__device__ __forceinline__ void spline8(float xv, const float* gk,
                                        float i1, float i2, float i3, float* b) {
    float t[11];
    #pragma unroll
    for (int j = 0; j < 11; j++)
        t[j] = (xv >= gk[j] && xv < gk[j + 1]) ? 1.0f : 0.0f;
    #pragma unroll
    for (int j = 0; j < 10; j++)
        t[j] = (xv - gk[j]) * i1 * t[j] + (gk[j + 2] - xv) * i1 * t[j + 1];
    #pragma unroll
    for (int j = 0; j < 9; j++)
        t[j] = (xv - gk[j]) * i2 * t[j] + (gk[j + 3] - xv) * i2 * t[j + 1];
    #pragma unroll
    for (int j = 0; j < 8; j++)
        b[j] = (xv - gk[j]) * i3 * t[j] + (gk[j + 4] - xv) * i3 * t[j + 1];
}

// ---------------------------------------------------------------------------
// Prep: combined KAN weights in mma B-fragment layout, fp16x2 split.
// ---------------------------------------------------------------------------
__global__ void prep_w(const float* __restrict__ bw1, const float* __restrict__ sw1,
                       const float* __restrict__ sc1,
                       const float* __restrict__ bw2, const float* __restrict__ sw2,
                       const float* __restrict__ sc2) {
    int idx = blockIdx.x * blockDim.x + threadIdx.x;
    const int per = HID * KTOT;
    if (idx >= 2 * per) return;
    int l = idx / per, t = idx - l * per;
    int o = t / KTOT, k = t - o * KTOT;
    const float* bw = l ? bw2 : bw1;
    const float* sw = l ? sw2 : sw1;
    const float* sc = l ? sc2 : sc1;
    float v;
    if (k < HID) v = bw[o * HID + k];
    else { int m = k - HID; int i = m >> 3; int cc = m & 7; v = sw[(o * HID + i) * 8 + cc] * sc[o * HID + i]; }
    __half s[2];
    split2(v, s);
    int chunk = k >> 5, kk = k & 31, ks = kk >> 4, kb = kk & 15;
    int reg = kb >> 3, k8 = kb & 7, half = kb & 1;
    int wn = o >> 6, nt = (o >> 3) & 7, n8 = o & 7;
    int lane = n8 * 4 + (k8 >> 1);
    int u = (((wn * 2 + ks) * 8 + nt) * 32 + lane) * 2 + reg;
    size_t base = ((size_t)(l * 36 + chunk)) * 2 * 4096;
    g_WB[base + u * 2 + half] = s[0];
    g_WB[base + 4096 + u * 2 + half] = s[1];
}

// Normalized prototypes in fragment layout, fp16x2 split.
__global__ void prep_p(const float* __restrict__ p) {
    int n = threadIdx.x;   // 256 threads, one proto each
    float sm = 0.f;
    for (int j = 0; j < HID; j++) { float v = p[n * HID + j]; sm += v * v; }
    float inv = 1.0f / fmaxf(sqrtf(sm), 1e-8f);
    int pass = n >> 7, np = n & 127;
    int wn = np >> 6, nt = (np >> 3) & 7, n8 = np & 7;
    for (int k = 0; k < HID; k++) {
        float v = p[n * HID + k] * inv;
        __half s[2];
        split2(v, s);
        int chunk = k >> 5, kk = k & 31, ks = kk >> 4, kb = kk & 15;
        int reg = kb >> 3, k8 = kb & 7, half = kb & 1;
        int lane = n8 * 4 + (k8 >> 1);
        int u = (((wn * 2 + ks) * 8 + nt) * 32 + lane) * 2 + reg;
        size_t base = ((size_t)(pass * 4 + chunk)) * 2 * 4096;
        g_PB[base + u * 2 + half] = s[0];
        g_PB[base + 4096 + u * 2 + half] = s[1];
    }
}

// ---------------------------------------------------------------------------
// A-fragment generation into smem (2 fp16 comps, paired u32 stores)
// mode 0 = layer (silu chunks 0..3, spline chunks 4..35); mode 1 = sim (plain)
// ---------------------------------------------------------------------------
__device__ __forceinline__ void genA(int mode, int c, uint32_t* A, const float* hs,
                                     const float* gk, float i1, float i2, float i3, int tid) {
    int r = tid & 127, half = tid >> 7;
    int ms = r >> 5, rr = r & 31, t = rr >> 4, fr = rr & 15;
    int regbase  = (fr >= 8) ? 1 : 0;
    int lanebase = (fr & 7) * 4;
    int fragbase = (ms * 2 + t) * 2;
    if (mode == 1 || c < 4) {
        const float* src = hs + r * 132 + c * 32 + half * 16;
        #pragma unroll
        for (int j = 0; j < 8; j++) {
            int kk = half * 16 + j * 2;
            float v0 = src[j * 2], v1 = src[j * 2 + 1];
            if (mode == 0) {
                v0 = v0 * (1.0f / (1.0f + __expf(-v0)));
                v1 = v1 * (1.0f / (1.0f + __expf(-v1)));
            }
            uint32_t cc2[2];
            split2x2(v0, v1, cc2);
            int ks = kk >> 4, kb = kk & 15;
            int reg = regbase + ((kb >= 8) ? 2 : 0);
            int lane = lanebase + ((kb & 7) >> 1);
            int u = ((fragbase + ks) * 32 + lane) * 4 + reg;
            A[u] = cc2[0]; A[2048 + u] = cc2[1];
        }
    } else {                                        // spline block: 4 channels
        int m = c - 4;
        #pragma unroll
        for (int pp = 0; pp < 2; pp++) {
            int ch = half + 2 * pp;
            float xv = hs[r * 132 + m * 4 + ch];
            float b[8];
            spline8(xv, gk, i1, i2, i3, b);
            #pragma unroll
            for (int j = 0; j < 4; j++) {
                int kk = ch * 8 + j * 2;
                uint32_t cc2[2];
                split2x2(b[j * 2], b[j * 2 + 1], cc2);
                int ks = kk >> 4, kb = kk & 15;
                int reg = regbase + ((kb >= 8) ? 2 : 0);
                int lane = lanebase + ((kb & 7) >> 1);
                int u = ((fragbase + ks) * 32 + lane) * 4 + reg;
                A[u] = cc2[0]; A[2048 + u] = cc2[1];
            }
        }
    }
}

// one K-chunk into a FRESH sub-accumulator: fp16x2 3-product (96 mma / warp)
__device__ __forceinline__ void mma_chunk(float sub[2][8][4], const uint32_t* As, const uint32_t* Bs,
                                          int ms, int wn, int lane) {
    #pragma unroll
    for (int ks = 0; ks < 2; ks++) {
        uint4 a[2][2];
        #pragma unroll
        for (int cc = 0; cc < 2; cc++)
            #pragma unroll
            for (int t = 0; t < 2; t++)
                a[cc][t] = *(const uint4*)(As + cc * 2048 + (((ms * 2 + t) * 2 + ks) * 32 + lane) * 4);
        #pragma unroll
        for (int nt = 0; nt < 8; nt++) {
            uint2 b0 = *(const uint2*)(Bs +        (((wn * 2 + ks) * 8 + nt) * 32 + lane) * 2);
            uint2 b1 = *(const uint2*)(Bs + 2048 + (((wn * 2 + ks) * 8 + nt) * 32 + lane) * 2);
            #pragma unroll
            for (int t = 0; t < 2; t++) {
                mma16(sub[t][nt], a[1][t], b0);   // a2*b1  (small first)
                mma16(sub[t][nt], a[0][t], b1);   // a1*b2
                mma16(sub[t][nt], a[0][t], b0);   // a1*b1
            }
        }
    }
}

// pipelined GEMM: cp.async B(c+1) + genA(c+1) overlap mma(c);
// per-chunk sub-accumulator merged into acc (kills accumulation-order noise)
__device__ __forceinline__ void run_gemm(float acc[2][8][4], const __half* gsrc, int nc, int mode,
                                         char* smc, uint32_t sb, const float* hs, const float* gk,
                                         float i1, float i2, float i3,
                                         int tid, int ms, int wn, int lane) {
    {   // prologue: fill stage 0
        uint32_t bd = sb + SM_B;
        const char* src = (const char*)gsrc;
        #pragma unroll
        for (int i = 0; i < 4; i++) cp16(bd + tid * 16 + i * 4096, src + tid * 16 + i * 4096);
        asm volatile("cp.async.commit_group;");
        genA(mode, 0, (uint32_t*)(smc + SM_A), hs, gk, i1, i2, i3, tid);
        asm volatile("cp.async.wait_group 0;" ::: "memory");
        __syncthreads();
    }
    for (int c = 0; c < nc; c++) {
        int s = c & 1;
        if (c + 1 < nc) {
            uint32_t bd = sb + SM_B + (s ^ 1) * 16384;
            const char* src = (const char*)(gsrc + (size_t)(c + 1) * 8192);
            #pragma unroll
            for (int i = 0; i < 4; i++) cp16(bd + tid * 16 + i * 4096, src + tid * 16 + i * 4096);
            asm volatile("cp.async.commit_group;");
            genA(mode, c + 1, (uint32_t*)(smc + SM_A + (s ^ 1) * 16384), hs, gk, i1, i2, i3, tid);
        }
        float sub[2][8][4];
        #pragma unroll
        for (int t = 0; t < 2; t++)
            #pragma unroll
            for (int nt = 0; nt < 8; nt++)
                #pragma unroll
                for (int rg = 0; rg < 4; rg++) sub[t][nt][rg] = 0.f;
        mma_chunk(sub, (const uint32_t*)(smc + SM_A + s * 16384),
                       (const uint32_t*)(smc + SM_B + s * 16384), ms, wn, lane);
        #pragma unroll
        for (int t = 0; t < 2; t++)
            #pragma unroll
            for (int nt = 0; nt < 8; nt++)
                #pragma unroll
                for (int rg = 0; rg < 4; rg++) acc[t][nt][rg] += sub[t][nt][rg];
        if (c + 1 < nc) asm volatile("cp.async.wait_group 0;" ::: "memory");
        __syncthreads();
    }
}

// ---------------------------------------------------------------------------
// Fused kernel: x -> KAN layer1 -> layer2 (emb out) -> mma sim argmax
// ---------------------------------------------------------------------------
__global__ void __launch_bounds__(THREADS, 1)
kan_mma(const float* __restrict__ x, const float* __restrict__ grid,
        float* __restrict__ out_emb, float* __restrict__ out_asn) {
    extern __shared__ char smc[];
    uint32_t sb = smem_u32(smc);
    float* hs = (float*)(smc + SM_HS);
    int tid = threadIdx.x, lane = tid & 31, wid = tid >> 5;
    int ms = wid & 3, wn = wid >> 2;
    int row0 = blockIdx.x * 128;

    // load x tile 128x128 (coalesced float4)
    #pragma unroll
    for (int q = 0; q < 16; q++) {
        int v = tid + THREADS * q;
        int r = v >> 5, c4 = v & 31;
        float4 xv = ((const float4*)x)[(size_t)row0 * 32 + v];
        *(float4*)(hs + r * 132 + c4 * 4) = xv;
    }
    float gk[12];
    #pragma unroll
    for (int j = 0; j < 12; j++) gk[j] = grid[j];   // all grid rows identical
    float i1 = 1.0f / (gk[1] - gk[0]);
    float i2 = 1.0f / (gk[2] - gk[0]);
    float i3 = 1.0f / (gk[3] - gk[0]);
    __syncthreads();

    float acc[2][8][4];

    // ---- two KAN layers ----
    for (int layer = 0; layer < 2; layer++) {
        #pragma unroll
        for (int t = 0; t < 2; t++)
            #pragma unroll
            for (int nt = 0; nt < 8; nt++)
                #pragma unroll
                for (int rg = 0; rg < 4; rg++) acc[t][nt][rg] = 0.f;

        run_gemm(acc, g_WB + (size_t)layer * 36 * 8192, 36, 0,
                 smc, sb, hs, gk, i1, i2, i3, tid, ms, wn, lane);

        // epilogue: acc -> hs (m16n8 C layout)
        #pragma unroll
        for (int t = 0; t < 2; t++)
            #pragma unroll
            for (int nt = 0; nt < 8; nt++) {
                int row = ms * 32 + t * 16 + (lane >> 2);
                int col = wn * 64 + nt * 8 + 2 * (lane & 3);
                *(float2*)(hs + row * 132 + col)       = make_float2(acc[t][nt][0], acc[t][nt][1]);
                *(float2*)(hs + (row + 8) * 132 + col) = make_float2(acc[t][nt][2], acc[t][nt][3]);
            }
        __syncthreads();
    }

    // emb out (coalesced float4 from hs)
    #pragma unroll
    for (int q = 0; q < 16; q++) {
        int v = tid + THREADS * q;
        int r = v >> 5, c4 = v & 31;
        float4 e = *(const float4*)(hs + r * 132 + c4 * 4);
        ((float4*)out_emb)[(size_t)row0 * 32 + v] = e;
    }

    // ---- cosine-sim via mma: 2 passes of 128 protos; argmax kept in regs ----
    float bestv[2][2]; int besti[2][2];
    #pragma unroll
    for (int t = 0; t < 2; t++)
        #pragma unroll
        for (int rh = 0; rh < 2; rh++) { bestv[t][rh] = -3.4e38f; besti[t][rh] = 0; }

    for (int p = 0; p < 2; p++) {
        #pragma unroll
        for (int t = 0; t < 2; t++)
            #pragma unroll
            for (int nt = 0; nt < 8; nt++)
                #pragma unroll
                for (int rg = 0; rg < 4; rg++) acc[t][nt][rg] = 0.f;

        run_gemm(acc, g_PB + (size_t)p * 4 * 8192, 4, 1,
                 smc, sb, hs, gk, i1, i2, i3, tid, ms, wn, lane);

        // merge this pass into per-thread best (ascending proto index order)
        #pragma unroll
        for (int t = 0; t < 2; t++)
            #pragma unroll
            for (int rh = 0; rh < 2; rh++)
                #pragma unroll
                for (int nt = 0; nt < 8; nt++)
                    #pragma unroll
                    for (int b = 0; b < 2; b++) {
                        float v2 = acc[t][nt][rh * 2 + b];
                        int idx = p * 128 + wn * 64 + nt * 8 + 2 * (lane & 3) + b;
                        if (v2 > bestv[t][rh]) { bestv[t][rh] = v2; besti[t][rh] = idx; }
                    }
    }

    // reduce across the 4 lanes sharing each row (lane^1, lane^2); lower index wins ties
    #pragma unroll
    for (int t = 0; t < 2; t++)
        #pragma unroll
        for (int rh = 0; rh < 2; rh++) {
            float v = bestv[t][rh]; int bi = besti[t][rh];
            #pragma unroll
            for (int off = 1; off <= 2; off <<= 1) {
                float ov = __shfl_xor_sync(0xffffffffu, v, off);
                int   oi = __shfl_xor_sync(0xffffffffu, bi, off);
                if (ov > v || (ov == v && oi < bi)) { v = ov; bi = oi; }
            }
            bestv[t][rh] = v; besti[t][rh] = bi;
        }
    __syncthreads();   // all sim smem reads done -> hs reusable as red

    float* red = (float*)(smc + SM_HS);
    if ((lane & 3) == 0) {
        #pragma unroll
        for (int t = 0; t < 2; t++)
            #pragma unroll
            for (int rh = 0; rh < 2; rh++) {
                int row = ms * 32 + t * 16 + (lane >> 2) + rh * 8;
                red[row * 4 + wn * 2] = bestv[t][rh];
                ((int*)red)[row * 4 + wn * 2 + 1] = besti[t][rh];
            }
    }
    __syncthreads();
    if (tid < 128) {
        float v0 = red[tid * 4];     int i0 = ((int*)red)[tid * 4 + 1];
        float v1 = red[tid * 4 + 2]; int i1b = ((int*)red)[tid * 4 + 3];
        // wn=0 covers lower proto indices within each pass; on ties prefer lower index
        int pick1 = (v1 > v0) || (v1 == v0 && i1b < i0);
        out_asn[row0 + tid] = (float)(pick1 ? i1b : i0);
    }
}

// ---------------------------------------------------------------------------
extern "C" void kernel_launch(void* const* d_in, const int* in_sizes, int n_in,
                              void* d_out, int out_size) {
    const float* x      = (const float*)d_in[0];
    const float* protos = (const float*)d_in[1];
    const float* grid   = (const float*)d_in[2];
    const float* bw1    = (const float*)d_in[3];
    const float* sw1    = (const float*)d_in[4];
    const float* sc1    = (const float*)d_in[5];
    const float* bw2    = (const float*)d_in[6];
    const float* sw2    = (const float*)d_in[7];
    const float* sc2    = (const float*)d_in[8];

    int n = in_sizes[0] / HID;
    float* out_emb = (float*)d_out;
    float* out_asn = out_emb + (size_t)n * HID;

    prep_w<<<(2 * HID * KTOT + 255) / 256, 256>>>(bw1, sw1, sc1, bw2, sw2, sc2);
    prep_p<<<1, 256>>>(protos);

    cudaFuncSetAttribute(kan_mma, cudaFuncAttributeMaxDynamicSharedMemorySize, SMEM_BYTES);
    kan_mma<<<n / 128, THREADS, SMEM_BYTES>>>(x, grid, out_emb, out_asn);
}